// round 10
// baseline (speedup 1.0000x reference)
#include <cuda_runtime.h>

#define BS_      128
#define NF_      4
#define P_LO_    1024
#define P_HI_    16384
#define K_       9
#define NC_      36
#define THREADS_ 512
#define TILE_    512                  // hi points per CTA (PPT=1)
#define NTILES_  (P_HI_ / TILE_)      // 32
#define PADROW_  36                   // padded lo-row stride (floats); 144B % 16 == 0
#define PADSZ_   (32 * PADROW_)       // 1152 floats per staged tile

// Scratch for class grouping (allocation-free: __device__ globals).
__device__ int g_cls_count[NC_];
__device__ int g_cls_list[NC_][BS_];

// Deterministic prepass: one warp per class, ballot+popc prefix keeps batch order.
__global__ void build_lists_kernel(const int* __restrict__ cls_ids) {
    int w    = (blockIdx.x * blockDim.x + threadIdx.x) >> 5;   // class id
    int lane = threadIdx.x & 31;
    if (w >= NC_) return;
    int base = 0;
    #pragma unroll
    for (int chunk = 0; chunk < BS_ / 32; chunk++) {
        int i = chunk * 32 + lane;
        int v = cls_ids[i];
        unsigned m = __ballot_sync(0xffffffffu, v == w);
        if (v == w) {
            int rank = __popc(m & ((1u << lane) - 1));
            g_cls_list[w][base + rank] = i;
        }
        base += __popc(m);
    }
    if (lane == 0) g_cls_count[w] = base;
}

// One CTA per (class, feature, 512-pt hi tile), one hi point per thread.
// The staged lo tile uses a PADDED row stride (36 floats) so the 3x3 stencil
// rows land in different banks -> conflict-free scalar gathers. Double
// buffered, x prefetched, one sync per sample.
__global__ void __launch_bounds__(THREADS_, 2)
upsample_kernel(const float* __restrict__ x,
                const int*   __restrict__ nbr,
                const float* __restrict__ wmap,
                const float* __restrict__ blo,
                const float* __restrict__ bhi,
                float*       __restrict__ out)
{
    __shared__ float y_sh[2][PADSZ_];      // 2 x 4608 B

    const int tile = blockIdx.x;
    const int f    = blockIdx.y;
    const int c    = blockIdx.z;
    const int n    = g_cls_count[c];
    if (n == 0) return;                       // block-uniform exit (before syncs)

    const int tid = threadIdx.x;
    const int p0  = tile * TILE_ + tid;       // this thread's hi point

    // ---- tile-constant state (once per CTA) ----
    const float* wp = wmap + (((size_t)c * NF_ + f) * P_HI_ + (size_t)p0) * K_;
    float wv[K_];
    #pragma unroll
    for (int k = 0; k < K_; k++) wv[k] = __ldg(wp + k);

    const int* ip = nbr + (size_t)p0 * K_;
    int nb[K_];
    #pragma unroll
    for (int k = 0; k < K_; k++) {
        int v = __ldg(ip + k);
        nb[k] = (v >> 5) * PADROW_ + (v & 31);   // remap to padded layout
    }

    const float bh = bhi[((size_t)c * NF_ + f) * P_HI_ + p0];

    // staging: thread covers lo points 2*tid, 2*tid+1 (same lo row; col even)
    const int srow  = (2 * tid) >> 5;
    const int scol  = (2 * tid) & 31;
    const int soff  = srow * PADROW_ + scol;

    const float2 bv = reinterpret_cast<const float2*>(
        blo + ((size_t)c * NF_ + f) * P_LO_)[tid];

    const float2* xb = reinterpret_cast<const float2*>(x);  // (b*4+f)*512 + tid

    // prefetch sample 0
    int b = g_cls_list[c][0];
    float2 xa = xb[((size_t)b * NF_ + f) * (P_LO_ / 2) + tid];

    for (int s = 0; s < n; s++) {
        float* buf = y_sh[s & 1];
        *reinterpret_cast<float2*>(buf + soff) =
            make_float2(xa.x - bv.x, xa.y - bv.y);

        const int b_cur = b;
        if (s + 1 < n) {                       // prefetch next sample's x
            b  = g_cls_list[c][s + 1];
            xa = xb[((size_t)b * NF_ + f) * (P_LO_ / 2) + tid];
        }

        __syncthreads();                       // staging visible; prev compute done

        float sum = bh;
        #pragma unroll
        for (int k = 0; k < K_; k++)
            sum = fmaf(wv[k], buf[nb[k]], sum);

        out[((size_t)b_cur * NF_ + f) * P_HI_ + p0] = sum;
        // no trailing sync: next sample writes the other buffer; sync(s+1)
        // orders this sample's reads before sample s+2's overwrite.
    }
}

extern "C" void kernel_launch(void* const* d_in, const int* in_sizes, int n_in,
                              void* d_out, int out_size) {
    const float* x    = (const float*)d_in[0];   // (BS, NF*P_LO) f32
    const int*   cls  = (const int*)  d_in[1];   // (BS,) i32
    const int*   nbr  = (const int*)  d_in[2];   // (P_HI, K) i32
    const float* wmap = (const float*)d_in[3];   // (NC, NF, P_HI, K) f32
    const float* blo  = (const float*)d_in[4];   // (NC, NF, P_LO) f32
    const float* bhi  = (const float*)d_in[5];   // (NC, NF, P_HI) f32
    float* out = (float*)d_out;                  // (BS, NF, P_HI) f32

    build_lists_kernel<<<2, 576>>>(cls);         // 36 warps, one per class
    dim3 grid(NTILES_, NF_, NC_);
    upsample_kernel<<<grid, THREADS_>>>(x, nbr, wmap, blo, bhi, out);
}

// round 13
// speedup vs baseline: 1.2350x; 1.2350x over previous
#include <cuda_runtime.h>

#define BS_    128
#define NF_    4
#define P_LO_  1024
#define P_HI_  16384
#define K_     9
#define NC_    36

// Allocation-free scratch.
__device__ int g_cls_count[NC_];
__device__ int g_cls_list[NC_][BS_];
__device__ unsigned long long g_pack[P_HI_];   // per-point shuffle descriptor

// Merged prepass.
//  CTAs 0..63 : pack shuffle descriptors. Warp W = cta*8+wid covers hi rows
//               {2h,2h+1}, cols [16t,16t+16). Window base (r0,c0) = warp-min
//               of actual neighbor rows/cols. Shape mode (warp-uniform):
//                 mode0: rspan<=3 && cspan<=7  -> slot = dr*8 + dc
//                 mode1: rspan<=4 && cspan<=5  -> slot = dr*6 + dc (<=29)
//                 mode2: fallback (global gather in main kernel)
//               pk bits: sl_k @5k (k<9), r0 @45, c0 @50, mode @55.
//  CTAs 64..68: class lists, one warp per class (ballot keeps batch order).
__global__ void prepass_kernel(const int* __restrict__ cls_ids,
                               const int* __restrict__ nbr) {
    const int cta  = blockIdx.x;
    const int tid  = threadIdx.x;
    const int lane = tid & 31;
    if (cta < 64) {
        const int W = cta * 8 + (tid >> 5);
        const int h = W >> 3, t = W & 7;
        const int row = 2 * h + (lane >> 4);
        const int col = 16 * t + (lane & 15);
        const int p = row * 128 + col;
        int r[K_], c[K_];
        int rmin = 32, cmin = 32, rmax = -1, cmax = -1;
        #pragma unroll
        for (int k = 0; k < K_; k++) {
            int v = nbr[p * K_ + k];
            r[k] = v >> 5; c[k] = v & 31;
            rmin = min(rmin, r[k]);  rmax = max(rmax, r[k]);
            cmin = min(cmin, c[k]);  cmax = max(cmax, c[k]);
        }
        #pragma unroll
        for (int o = 16; o; o >>= 1) {
            rmin = min(rmin, __shfl_xor_sync(0xffffffffu, rmin, o));
            rmax = max(rmax, __shfl_xor_sync(0xffffffffu, rmax, o));
            cmin = min(cmin, __shfl_xor_sync(0xffffffffu, cmin, o));
            cmax = max(cmax, __shfl_xor_sync(0xffffffffu, cmax, o));
        }
        const int rspan = rmax - rmin, cspan = cmax - cmin;
        int mode;
        if (rspan <= 3 && cspan <= 7)      mode = 0;
        else if (rspan <= 4 && cspan <= 5) mode = 1;
        else                               mode = 2;

        unsigned long long pk = ((unsigned long long)rmin << 45) |
                                ((unsigned long long)cmin << 50) |
                                ((unsigned long long)mode << 55);
        if (mode < 2) {
            #pragma unroll
            for (int k = 0; k < K_; k++) {
                int dr = r[k] - rmin, dc = c[k] - cmin;
                unsigned long long sl =
                    (unsigned long long)(mode == 0 ? dr * 8 + dc : dr * 6 + dc);
                pk |= sl << (5 * k);
            }
        }
        g_pack[p] = pk;
    } else {
        const int w = (cta - 64) * 8 + (tid >> 5);
        if (w < NC_) {
            int base = 0;
            #pragma unroll
            for (int chunk = 0; chunk < BS_ / 32; chunk++) {
                int i = chunk * 32 + lane;
                int v = cls_ids[i];
                unsigned m = __ballot_sync(0xffffffffu, v == w);
                if (v == w)
                    g_cls_list[w][base + __popc(m & ((1u << lane) - 1))] = i;
                base += __popc(m);
            }
            if (lane == 0) g_cls_count[w] = base;
        }
    }
}

// Warp-autonomous main kernel: NO shared memory, NO barriers.
// Each lane stages one lo-window value in a register; gathers are shuffles.
__global__ void __launch_bounds__(256, 5)
upsample_kernel(const float* __restrict__ x,
                const int*   __restrict__ nbr,
                const float* __restrict__ wmap,
                const float* __restrict__ blo,
                const float* __restrict__ bhi,
                float*       __restrict__ out)
{
    const int f = blockIdx.y;
    const int c = blockIdx.z;
    const int n = g_cls_count[c];
    if (n == 0) return;

    const int tid  = threadIdx.x;
    const int lane = tid & 31;
    const int W = blockIdx.x * 8 + (tid >> 5);
    const int h = W >> 3, t = W & 7;
    const int row = 2 * h + (lane >> 4);
    const int col = 16 * t + (lane & 15);
    const int p = row * 128 + col;

    // weights + bias_high for this point
    const float* wp = wmap + (((size_t)c * NF_ + f) * P_HI_ + (size_t)p) * K_;
    float wv[K_];
    #pragma unroll
    for (int k = 0; k < K_; k++) wv[k] = wp[k];
    const float bh = bhi[((size_t)c * NF_ + f) * P_HI_ + p];

    const float* blo_cf = blo + ((size_t)c * NF_ + f) * P_LO_;
    const float* x_f    = x   + (size_t)f * P_LO_;
    float*       obase  = out + (size_t)f * P_HI_ + p;

    const unsigned long long pk = g_pack[p];
    const int mode = (int)((pk >> 55) & 3);

    if (mode < 2) {
        const int r0 = (int)((pk >> 45) & 31);
        const int c0 = (int)((pk >> 50) & 31);
        int sl[K_];
        #pragma unroll
        for (int k = 0; k < K_; k++) sl[k] = (int)((pk >> (5 * k)) & 31);

        // this lane's staged lo point (slot -> grid; clamped slots never referenced)
        const int srow = min(r0 + (mode == 0 ? (lane >> 3) : lane / 6), 31);
        const int scol = min(c0 + (mode == 0 ? (lane & 7)  : lane % 6), 31);
        const int sidx = srow * 32 + scol;

        const float blo_s = blo_cf[sidx];
        const float* xbase = x_f + sidx;

        int b = g_cls_list[c][0];
        float xv = xbase[(size_t)b * (NF_ * P_LO_)];
        for (int s = 0; s < n; s++) {
            const float y = xv - blo_s;
            const int bc = b;
            if (s + 1 < n) {
                b  = g_cls_list[c][s + 1];
                xv = xbase[(size_t)b * (NF_ * P_LO_)];
            }
            float acc = bh;
            #pragma unroll
            for (int k = 0; k < K_; k++)
                acc = fmaf(wv[k], __shfl_sync(0xffffffffu, y, sl[k]), acc);
            obase[(size_t)bc * (NF_ * P_HI_)] = acc;
        }
    } else {
        // Safety net: direct global gather (expected never / rarely taken).
        int nb[K_];
        float blo_nb[K_];
        #pragma unroll
        for (int k = 0; k < K_; k++) {
            nb[k]     = nbr[p * K_ + k];
            blo_nb[k] = blo_cf[nb[k]];
        }
        for (int s = 0; s < n; s++) {
            const int b = g_cls_list[c][s];
            const float* xs = x_f + (size_t)b * (NF_ * P_LO_);
            float acc = bh;
            #pragma unroll
            for (int k = 0; k < K_; k++)
                acc = fmaf(wv[k], xs[nb[k]] - blo_nb[k], acc);
            obase[(size_t)b * (NF_ * P_HI_)] = acc;
        }
    }
}

extern "C" void kernel_launch(void* const* d_in, const int* in_sizes, int n_in,
                              void* d_out, int out_size) {
    const float* x    = (const float*)d_in[0];   // (BS, NF*P_LO) f32
    const int*   cls  = (const int*)  d_in[1];   // (BS,) i32
    const int*   nbr  = (const int*)  d_in[2];   // (P_HI, K) i32
    const float* wmap = (const float*)d_in[3];   // (NC, NF, P_HI, K) f32
    const float* blo  = (const float*)d_in[4];   // (NC, NF, P_LO) f32
    const float* bhi  = (const float*)d_in[5];   // (NC, NF, P_HI) f32
    float* out = (float*)d_out;                  // (BS, NF, P_HI) f32

    prepass_kernel<<<69, 256>>>(cls, nbr);
    dim3 grid(64, NF_, NC_);
    upsample_kernel<<<grid, 256>>>(x, nbr, wmap, blo, bhi, out);
}